// round 1
// baseline (speedup 1.0000x reference)
#include <cuda_runtime.h>

// x: (8, 64, 128, 128) fp32  ->  out: (8, 64, 384, 384) fp32
//
// For output (3i+ki, 3j+kj):
//   ki/kj == 1 : exact sample
//   ki/kj == 0 : 0.5*(left/up reflect-neighbor + center)
//   ki/kj == 2 : 0.5*(center + right/down reflect-neighbor)
// Reflect (pad=1, mode='reflect'): index -1 -> 1, index 128 -> 126.

#define H 128
#define W 128
#define OW 384

__global__ __launch_bounds__(384) void rf_scale_kernel(
    const float* __restrict__ x, float* __restrict__ out, int n_bc)
{
    const int i  = blockIdx.x;     // input row 0..127
    const int bc = blockIdx.y;     // fused batch*channel
    const int t  = threadIdx.x;    // 0..383

    __shared__ float a[W];         // row refl(i-1)
    __shared__ float b[W];         // row i
    __shared__ float c[W];         // row refl(i+1)
    __shared__ float r[3][W + 2];  // combined rows with 1-col reflect halo

    const float* __restrict__ xin = x + (size_t)bc * (H * W);

    const int ri0 = (i == 0)     ? 1       : i - 1;
    const int ri2 = (i == H - 1) ? (H - 2) : i + 1;

    // Coalesced load of the three source rows (384 threads -> 3*128 elems)
    if (t < W) {
        a[t] = xin[ri0 * W + t];
    } else if (t < 2 * W) {
        const int col = t - W;
        b[col] = xin[i * W + col];
    } else {
        const int col = t - 2 * W;
        c[col] = xin[ri2 * W + col];
    }
    __syncthreads();

    // Build the 3 vertically-combined rows, with column-reflect halo.
    // r[ki][p] corresponds to padded column p (p=0..129).
    if (t < W + 2) {
        int q = t - 1;
        q = (q < 0) ? 1 : ((q > W - 1) ? (W - 2) : q);
        const float av = a[q];
        const float bv = b[q];
        const float cv = c[q];
        r[0][t] = 0.5f * (av + bv);
        r[1][t] = bv;
        r[2][t] = 0.5f * (bv + cv);
    }
    __syncthreads();

    // Each thread owns one output column t = 3*j + kj; writes 3 output rows.
    const int j  = t / 3;
    const int kj = t - 3 * j;

    const float w0 = (kj == 0) ? 0.5f : 0.0f;
    const float w1 = (kj == 1) ? 1.0f : 0.5f;
    const float w2 = (kj == 2) ? 0.5f : 0.0f;

    float* __restrict__ o =
        out + (size_t)bc * (OW * OW) + (size_t)(3 * i) * OW + t;

    #pragma unroll
    for (int ki = 0; ki < 3; ki++) {
        const float v = w0 * r[ki][j] + w1 * r[ki][j + 1] + w2 * r[ki][j + 2];
        o[ki * OW] = v;
    }
}

extern "C" void kernel_launch(void* const* d_in, const int* in_sizes, int n_in,
                              void* d_out, int out_size)
{
    const float* x = (const float*)d_in[0];
    float* out = (float*)d_out;

    const int n_bc = in_sizes[0] / (H * W);   // 8*64 = 512

    dim3 grid(H, n_bc);
    dim3 block(384);
    rf_scale_kernel<<<grid, block>>>(x, out, n_bc);
}

// round 2
// speedup vs baseline: 1.5525x; 1.5525x over previous
#include <cuda_runtime.h>

// x: (8, 64, 128, 128) fp32  ->  out: (8, 64, 384, 384) fp32
//
// out[bc][3i+ki][3j+kj]:
//   vertical:   ki=0 -> 0.5*(x[refl(i-1)] + x[i]);  ki=1 -> x[i];  ki=2 -> 0.5*(x[i] + x[refl(i+1)])
//   horizontal: kj=0 -> 0.5*(c[refl(j-1)] + c[j]);  kj=1 -> c[j];  kj=2 -> 0.5*(c[j] + c[refl(j+1)])
// reflect (pad=1): -1 -> 1, 128 -> 126.
//
// Warp-per-output-row. Lane u owns input cols 4u..4u+3 (one float4) and
// output cols 12u..12u+11 (three float4). Column halo via 2 shuffles.
// Note out[3j+2] == out[3(j+1)] (same average), so 5 averages cover 12 outputs.

#define H 128
#define W 128
#define W4 (W / 4)
#define OW 384
#define OW4 (OW / 4)

__global__ __launch_bounds__(384) void rf_scale_kernel(
    const float4* __restrict__ x, float4* __restrict__ out)
{
    const int lane = threadIdx.x & 31;
    const int w    = threadIdx.x >> 5;          // 0..11
    const int il   = w >> 2;                    // trick? no: need w/3
    (void)il;

    const int iw   = (w * 0x5556) >> 16;        // w/3 for w in 0..11 (exact)
    const int ki   = w - 3 * iw;

    const int i  = (blockIdx.x << 2) + iw;      // input row 0..127
    const int bc = blockIdx.y;

    const float4* __restrict__ xin = x + (size_t)bc * (H * W4);

    // Vertical pair of rows (ki==1 -> both = i, exact since 0.5*(b+b)==b)
    const int rowA = (ki == 0) ? ((i == 0) ? 1 : i - 1) : i;
    const int rowB = (ki == 2) ? ((i == H - 1) ? H - 2 : i + 1) : i;

    const float4 a = xin[rowA * W4 + lane];
    const float4 b = xin[rowB * W4 + lane];

    float4 f;
    f.x = 0.5f * (a.x + b.x);
    f.y = 0.5f * (a.y + b.y);
    f.z = 0.5f * (a.z + b.z);
    f.w = 0.5f * (a.w + b.w);

    // Column halo: c[4u-1] and c[4u+4]
    float cm1 = __shfl_up_sync(0xffffffffu, f.w, 1);
    float cp1 = __shfl_down_sync(0xffffffffu, f.x, 1);
    if (lane == 0)  cm1 = f.y;   // c[-1]  = c[1]   (reflect)
    if (lane == 31) cp1 = f.z;   // c[128] = c[126] (reflect)

    const float h0 = 0.5f * (cm1 + f.x);
    const float h1 = 0.5f * (f.x + f.y);
    const float h2 = 0.5f * (f.y + f.z);
    const float h3 = 0.5f * (f.z + f.w);
    const float h4 = 0.5f * (f.w + cp1);

    // 12 outputs for cols 12u..12u+11
    const float4 v0 = make_float4(h0,  f.x, h1,  h1);
    const float4 v1 = make_float4(f.y, h2,  h2,  f.z);
    const float4 v2 = make_float4(h3,  h3,  f.w, h4);

    float4* __restrict__ o =
        out + (size_t)bc * (OW * OW4) + (size_t)(3 * i + ki) * OW4 + 3 * lane;

    o[0] = v0;
    o[1] = v1;
    o[2] = v2;
}

extern "C" void kernel_launch(void* const* d_in, const int* in_sizes, int n_in,
                              void* d_out, int out_size)
{
    const float4* x = (const float4*)d_in[0];
    float4* out = (float4*)d_out;

    const int n_bc = in_sizes[0] / (H * W);   // 512

    dim3 grid(H / 4, n_bc);                   // (32, 512)
    dim3 block(384);
    rf_scale_kernel<<<grid, block>>>(x, out);
}

// round 3
// speedup vs baseline: 2.0452x; 1.3174x over previous
#include <cuda_runtime.h>

// x: (8, 64, 128, 128) fp32  ->  out: (8, 64, 384, 384) fp32
//
// out[bc][3i+ki][t], t = 3j+kj:
//   vertical blend (per output row, ki): c[j] = 0.5*(x[rowA][j] + x[rowB][j])
//     ki=0: rowA=refl(i-1), rowB=i; ki=1: rowA=rowB=i (exact); ki=2: rowA=i, rowB=refl(i+1)
//   horizontal: kj=0 -> h[j-1]; kj=1 -> c[j]; kj=2 -> h[j]
//     where h[j] = 0.5*(c[j] + c[refl(j+1)]); reflect: -1 -> 1, 128 -> 126.
//
// Warp-per-output-row. Phase 1: lane u computes c[4u..4u+3], h[4u..4u+3],
// stores to this warp's smem rows (aligned STS.128, conflict-free). Phase 2:
// lane u emits coalesced output float4s g = u, u+32, u+64 via 4 scalar LDS
// and selects. Full-sector, fully-coalesced stores.

#define H 128
#define W 128
#define W4 (W / 4)
#define OW 384
#define OW4 (OW / 4)
#define NWARP 12

__global__ __launch_bounds__(384) void rf_scale_kernel(
    const float4* __restrict__ x, float4* __restrict__ out)
{
    __shared__ float Cs[NWARP][W];   // vertically-blended row per warp
    __shared__ float Hs[NWARP][W];   // horizontal pair-averages per warp

    const int lane = threadIdx.x & 31;
    const int w    = threadIdx.x >> 5;           // 0..11

    const int iw = (w * 0x5556) >> 16;           // w/3 (exact for 0..11)
    const int ki = w - 3 * iw;

    const int i  = (blockIdx.x << 2) + iw;       // input row 0..127
    const int bc = blockIdx.y;

    const float4* __restrict__ xin = x + (size_t)bc * (H * W4);

    const int rowA = (ki == 0) ? ((i == 0) ? 1 : i - 1) : i;
    const int rowB = (ki == 2) ? ((i == H - 1) ? H - 2 : i + 1) : i;

    const float4 a = xin[rowA * W4 + lane];
    const float4 b = xin[rowB * W4 + lane];

    float4 c;
    c.x = 0.5f * (a.x + b.x);
    c.y = 0.5f * (a.y + b.y);
    c.z = 0.5f * (a.z + b.z);
    c.w = 0.5f * (a.w + b.w);

    // c[4u+4] from next lane (reflect at right edge: c[128] = c[126])
    float cp1 = __shfl_down_sync(0xffffffffu, c.x, 1);
    if (lane == 31) cp1 = c.z;

    float4 h;
    h.x = 0.5f * (c.x + c.y);
    h.y = 0.5f * (c.y + c.z);
    h.z = 0.5f * (c.z + c.w);
    h.w = 0.5f * (c.w + cp1);

    reinterpret_cast<float4*>(Cs[w])[lane] = c;
    reinterpret_cast<float4*>(Hs[w])[lane] = h;
    __syncwarp();

    const float* __restrict__ Cr = Cs[w];
    const float* __restrict__ Hr = Hs[w];

    float4* __restrict__ orow =
        out + (size_t)bc * (OW * OW4) + (size_t)(3 * i + ki) * OW4;

    #pragma unroll
    for (int s = 0; s < 3; s++) {
        const int g = lane + (s << 5);           // output float4 index 0..95
        const int q = (g << 2) / 3;
        const int r = (g << 2) - 3 * q;          // 0,1,2

        const float c0 = Cr[q];
        const float c1 = Cr[q + 1];
        const int  ql  = (r == 0) ? ((q == 0) ? 0 : q - 1) : q;  // h[-1] -> h[0]
        const int  qh  = (r == 2) ? q + 1 : q;
        const float hl = Hr[ql];
        const float hh = Hr[qh];

        float4 v;
        v.x = (r == 1) ? c0 : hl;
        v.y = (r == 0) ? c0 : hl;
        v.z = (r == 2) ? c1 : hh;
        v.w = (r == 1) ? c1 : hh;

        orow[g] = v;
    }
}

extern "C" void kernel_launch(void* const* d_in, const int* in_sizes, int n_in,
                              void* d_out, int out_size)
{
    const float4* x = (const float4*)d_in[0];
    float4* out = (float4*)d_out;

    const int n_bc = in_sizes[0] / (H * W);   // 512

    dim3 grid(H / 4, n_bc);                   // (32, 512)
    dim3 block(384);
    rf_scale_kernel<<<grid, block>>>(x, out);
}

// round 4
// speedup vs baseline: 2.1297x; 1.0413x over previous
#include <cuda_runtime.h>

// x: (8, 64, 128, 128) fp32  ->  out: (8, 64, 384, 384) fp32
//
// out[bc][3i+ki][3j+kj]:
//   vertical: c_ki[j], ki=0: 0.5*(x[refl(i-1)][j]+x[i][j]); ki=1: x[i][j];
//             ki=2: 0.5*(x[i][j]+x[refl(i+1)][j])
//   horizontal: kj=0 -> h[j-1], kj=1 -> c[j], kj=2 -> h[j],
//             h[j] = 0.5*(c[j]+c[refl(j+1)]);  reflect: -1 -> 1, 128 -> 126
//
// One warp per input row i, producing ALL THREE output rows (ki=0,1,2):
//  phase 1: 3x LDG.128 (rows i-1,i,i+1), vertical blends in regs,
//           3x STS.128 into padded smem rows (bank-conflict-free).
//  phase 2: per output float4 g: indices q=(4g)/3, r=4g-3q computed ONCE,
//           reused for all 3 ki rows; 3 scalar LDS + 2 flops recover
//           {c[q], c[q+1], h[.]}; fully coalesced full-sector STG.128.

#define H 128
#define W 128
#define W4 (W / 4)
#define OW 384
#define OW4 (OW / 4)
#define NW 8                 // warps per block
#define CPAD 144             // 128 + 4 pad per 32 (swizzle keeps 16B align)

__device__ __forceinline__ int swz(int j) { return j + ((j >> 5) << 2); }

__global__ __launch_bounds__(NW * 32) void rf_scale_kernel(
    const float4* __restrict__ x, float4* __restrict__ out)
{
    __shared__ float Cs[NW][3][CPAD];

    const int lane = threadIdx.x & 31;
    const int w    = threadIdx.x >> 5;          // 0..NW-1

    const int i  = blockIdx.x * NW + w;         // input row 0..127
    const int bc = blockIdx.y;

    const float4* __restrict__ xin = x + (size_t)bc * (H * W4);

    const int ra = (i == 0)     ? 1       : i - 1;
    const int rd = (i == H - 1) ? (H - 2) : i + 1;

    const float4 a = xin[ra * W4 + lane];
    const float4 b = xin[i  * W4 + lane];
    const float4 d = xin[rd * W4 + lane];

    float4 c0, c2;
    c0.x = 0.5f * (a.x + b.x);  c0.y = 0.5f * (a.y + b.y);
    c0.z = 0.5f * (a.z + b.z);  c0.w = 0.5f * (a.w + b.w);
    c2.x = 0.5f * (b.x + d.x);  c2.y = 0.5f * (b.y + d.y);
    c2.z = 0.5f * (b.z + d.z);  c2.w = 0.5f * (b.w + d.w);

    const int so = swz(lane << 2);              // 16B-aligned (pad multiple of 4)
    *reinterpret_cast<float4*>(&Cs[w][0][so]) = c0;
    *reinterpret_cast<float4*>(&Cs[w][1][so]) = b;   // ki=1: exact copy
    *reinterpret_cast<float4*>(&Cs[w][2][so]) = c2;
    __syncwarp();

    float4* __restrict__ obase =
        out + (size_t)bc * (OW * OW4) + (size_t)(3 * i) * OW4;

    #pragma unroll
    for (int s = 0; s < 3; s++) {
        const int g  = lane + (s << 5);                 // output float4 idx 0..95
        const int fg = g << 2;
        const int q  = (int)(((unsigned)fg * 21846u) >> 16);   // fg/3 exact here
        const int r  = fg - 3 * q;

        // third index: r==0 -> refl(q-1); r==2 -> refl(q+2); r==1 unused (any valid)
        const int qt = (r == 0) ? ((q == 0) ? 1 : q - 1)
                                : ((q == W - 2) ? (W - 2) : q + 2);

        const int aq  = swz(q);
        const int aq1 = swz(q + 1);
        const int at  = swz(qt);

        #pragma unroll
        for (int k = 0; k < 3; k++) {
            const float* __restrict__ C = Cs[w][k];
            const float cq  = C[aq];
            const float cq1 = C[aq1];
            const float ct  = C[at];

            const float h0 = 0.5f * (cq + cq1);
            const float ex = 0.5f * (ct + ((r == 0) ? cq : cq1));

            float4 v;
            v.x = (r == 0) ? ex  : ((r == 1) ? cq  : h0);
            v.y = (r == 0) ? cq  : h0;
            v.z = (r == 2) ? cq1 : h0;
            v.w = (r == 2) ? ex  : ((r == 1) ? cq1 : h0);

            obase[k * OW4 + g] = v;
        }
    }
}

extern "C" void kernel_launch(void* const* d_in, const int* in_sizes, int n_in,
                              void* d_out, int out_size)
{
    const float4* x = (const float4*)d_in[0];
    float4* out = (float4*)d_out;

    const int n_bc = in_sizes[0] / (H * W);   // 512

    dim3 grid(H / NW, n_bc);                  // (16, 512)
    dim3 block(NW * 32);                      // 256
    rf_scale_kernel<<<grid, block>>>(x, out);
}

// round 5
// speedup vs baseline: 2.1978x; 1.0320x over previous
#include <cuda_runtime.h>

// x: (8, 64, 128, 128) fp32  ->  out: (8, 64, 384, 384) fp32
//
// Row dedup: out[3i] == out[3(i-1)+2] (both = H(0.5*(x[i-1]+x[i]))),
// out[0]==out[2], out[381]==out[383]. Distinct rows: center(i)=H(x[i]) -> row 3i+1,
// avg(i)=H(0.5*(x[i]+x[i+1]))       -> rows 3i+2 and 3i+3 (i<127),
// plus edges: avg(0) -> row 0, avg(126) -> row 383.
// H() = horizontal 3x resample: out col 3j+kj: kj=0 -> h[j-1], kj=1 -> c[j],
// kj=2 -> h[j]; h[j]=0.5*(c[j]+c[refl(j+1)]); reflect: -1->1, 128->126.
//
// Warp per input row i: 2x LDG.128 (rows i, i+1), 2x STS.128 into padded smem,
// gather phase computes indices once per output-vec and reuses for both rows;
// all STG.128 fully coalesced / full-sector.

#define H 128
#define W 128
#define W4 (W / 4)
#define OW 384
#define OW4 (OW / 4)
#define NW 8
#define CPAD 144              // 128 + 4 pad per 32 floats (keeps 16B align)

__device__ __forceinline__ int swz(int j) { return j + ((j >> 5) << 2); }

__device__ __forceinline__ float4 gatherv(const float* __restrict__ C,
                                          int aq, int aq1, int at, int r)
{
    const float cq  = C[aq];
    const float cq1 = C[aq1];
    const float ct  = C[at];

    const float h0 = 0.5f * (cq + cq1);
    const float ex = 0.5f * (ct + ((r == 0) ? cq : cq1));

    float4 v;
    v.x = (r == 0) ? ex  : ((r == 1) ? cq  : h0);
    v.y = (r == 0) ? cq  : h0;
    v.z = (r == 2) ? cq1 : h0;
    v.w = (r == 2) ? ex  : ((r == 1) ? cq1 : h0);
    return v;
}

__global__ __launch_bounds__(NW * 32) void rf_scale_kernel(
    const float4* __restrict__ x, float4* __restrict__ out)
{
    __shared__ float Cs[NW][2][CPAD];   // [0] = center row, [1] = avg row

    const int lane = threadIdx.x & 31;
    const int w    = threadIdx.x >> 5;

    const int i  = blockIdx.x * NW + w;          // input row 0..127
    const int bc = blockIdx.y;

    const float4* __restrict__ xin = x + (size_t)bc * (H * W4);

    const int i1 = (i < H - 1) ? i + 1 : i;      // avg unused when i==127
    const float4 b = xin[i  * W4 + lane];
    const float4 d = xin[i1 * W4 + lane];

    float4 av;
    av.x = 0.5f * (b.x + d.x);
    av.y = 0.5f * (b.y + d.y);
    av.z = 0.5f * (b.z + d.z);
    av.w = 0.5f * (b.w + d.w);

    const int so = swz(lane << 2);
    *reinterpret_cast<float4*>(&Cs[w][0][so]) = b;
    *reinterpret_cast<float4*>(&Cs[w][1][so]) = av;
    __syncwarp();

    const float* __restrict__ Cc = Cs[w][0];
    const float* __restrict__ Ca = Cs[w][1];

    float4* __restrict__ obase =
        out + (size_t)bc * (OW * OW4) + (size_t)(3 * i) * OW4;

    const bool has_avg = (i < H - 1);
    const bool edge0   = (i == 0);
    const bool edge383 = (i == H - 2);

    #pragma unroll
    for (int s = 0; s < 3; s++) {
        const int g  = lane + (s << 5);                       // 0..95
        const int fg = g << 2;
        const int q  = (int)(((unsigned)fg * 21846u) >> 16);  // fg/3 (exact)
        const int r  = fg - 3 * q;

        const int qt = (r == 0) ? ((q == 0) ? 1 : q - 1)
                                : ((q == W - 2) ? (W - 2) : q + 2);

        const int aq  = swz(q);
        const int aq1 = swz(q + 1);
        const int at  = swz(qt);

        // center(i) -> row 3i+1
        obase[OW4 + g] = gatherv(Cc, aq, aq1, at, r);

        if (has_avg) {
            const float4 v = gatherv(Ca, aq, aq1, at, r);
            obase[2 * OW4 + g] = v;                 // row 3i+2
            obase[3 * OW4 + g] = v;                 // row 3i+3
            if (edge0)   obase[g] = v;              // row 0   = avg(0)
            if (edge383) obase[5 * OW4 + g] = v;    // row 383 = avg(126)
        }
    }
}

extern "C" void kernel_launch(void* const* d_in, const int* in_sizes, int n_in,
                              void* d_out, int out_size)
{
    const float4* x = (const float4*)d_in[0];
    float4* out = (float4*)d_out;

    const int n_bc = in_sizes[0] / (H * W);   // 512

    dim3 grid(H / NW, n_bc);                  // (16, 512)
    dim3 block(NW * 32);                      // 256
    rf_scale_kernel<<<grid, block>>>(x, out);
}